// round 1
// baseline (speedup 1.0000x reference)
#include <cuda_runtime.h>
#include <cstdint>

#define D     128
#define NSEG  4096
#define BM    64
#define SXS   132      // padded row stride (floats) for sX/sH tiles
#define CH    2048     // nodes per block in segment-sum

// ---------------- scratch (device globals; no allocation allowed) ----------
__device__ float g_xsum[NSEG * D];
__device__ float g_rho [NSEG * D];

// ---------------- packed f32x2 helpers -------------------------------------
__device__ __forceinline__ void fma2(unsigned long long& acc,
                                     unsigned long long a,
                                     unsigned long long b) {
    asm("fma.rn.f32x2 %0, %1, %2, %0;" : "+l"(acc) : "l"(a), "l"(b));
}
__device__ __forceinline__ unsigned long long pack2(float a) {
    unsigned long long d;
    asm("mov.b64 %0, {%1, %1};" : "=l"(d) : "f"(a));
    return d;
}
__device__ __forceinline__ float2 unpack2(unsigned long long v) {
    float2 r;
    asm("mov.b64 {%0, %1}, %2;" : "=f"(r.x), "=f"(r.y) : "l"(v));
    return r;
}

// ---------------- k0: zero the segment-sum accumulator ---------------------
__global__ void k_zero() {
    int i = blockIdx.x * blockDim.x + threadIdx.x;
    if (i < NSEG * D / 4)
        reinterpret_cast<float4*>(g_xsum)[i] = make_float4(0.f, 0.f, 0.f, 0.f);
}

// ---------------- k1: segment sum (idx sorted -> run accumulation) ---------
__global__ void k_segsum(const float* __restrict__ x,
                         const int*   __restrict__ idx, int n) {
    int f = threadIdx.x;                       // feature 0..127
    long start = (long)blockIdx.x * CH;
    if (start >= n) return;
    long end = start + CH; if (end > n) end = n;

    int   cur = __ldg(&idx[start]);
    float acc = 0.f;
    #pragma unroll 4
    for (long nn = start; nn < end; ++nn) {
        int   s = __ldg(&idx[nn]);
        float v = __ldg(&x[nn * D + f]);
        if (s != cur) {
            atomicAdd(&g_xsum[(long)cur * D + f], acc);
            acc = 0.f; cur = s;
        }
        acc += v;
    }
    atomicAdd(&g_xsum[(long)cur * D + f], acc);
}

// ---------------- k2: rho MLP on 4096 segment rows --------------------------
#define RSEG 32
__global__ void k_rho(const float* __restrict__ w1, const float* __restrict__ b1,
                      const float* __restrict__ w2, const float* __restrict__ b2) {
    extern __shared__ float sm[];
    float* sW = sm;                // D*D
    float* sX = sW + D * D;        // RSEG*D
    float* sH = sX + RSEG * D;     // RSEG*D
    float* sB = sH + RSEG * D;     // D
    int j = threadIdx.x;           // 128 threads
    int seg0 = blockIdx.x * RSEG;

    for (int r = 0; r < RSEG; r++)
        sX[r * D + j] = g_xsum[(seg0 + r) * D + j];
    for (int i = j; i < D * D; i += blockDim.x) sW[i] = w1[i];
    sB[j] = b1[j];
    __syncthreads();

    for (int r = 0; r < RSEG; r++) {
        float acc = sB[j];
        #pragma unroll 8
        for (int k = 0; k < D; k++) acc += sX[r * D + k] * sW[k * D + j];
        sH[r * D + j] = fmaxf(acc, 0.f);
    }
    __syncthreads();
    for (int i = j; i < D * D; i += blockDim.x) sW[i] = w2[i];
    sB[j] = b2[j];
    __syncthreads();

    for (int r = 0; r < RSEG; r++) {
        float acc = sB[j];
        #pragma unroll 8
        for (int k = 0; k < D; k++) acc += sH[r * D + k] * sW[k * D + j];
        g_rho[(seg0 + r) * D + j] = acc;
    }
}

// ---------------- k3: fused phi MLP + gather(rho_sum) ----------------------
// One register-tiled stage: C[m0..m0+3][j0..j0+7] += A[m][k] * W[k][j]
__device__ __forceinline__ void mma_stage(const float* __restrict__ sA,
                                          const float* __restrict__ sW,
                                          int m0, int j0,
                                          unsigned long long acc[4][4]) {
    #pragma unroll
    for (int r = 0; r < 4; r++)
        #pragma unroll
        for (int p = 0; p < 4; p++) acc[r][p] = 0ull;

    #pragma unroll 8
    for (int k = 0; k < D; k++) {
        ulonglong2 wa = *reinterpret_cast<const ulonglong2*>(&sW[k * D + j0]);
        ulonglong2 wb = *reinterpret_cast<const ulonglong2*>(&sW[k * D + j0 + 4]);
        #pragma unroll
        for (int r = 0; r < 4; r++) {
            unsigned long long av = pack2(sA[(m0 + r) * SXS + k]);
            fma2(acc[r][0], av, wa.x);
            fma2(acc[r][1], av, wa.y);
            fma2(acc[r][2], av, wb.x);
            fma2(acc[r][3], av, wb.y);
        }
    }
}

__global__ __launch_bounds__(256, 1)
void k_phi(const float* __restrict__ x, const int* __restrict__ idx,
           const float* __restrict__ w1, const float* __restrict__ b1,
           const float* __restrict__ w2, const float* __restrict__ b2,
           float* __restrict__ out, int n) {
    extern __shared__ float sm[];
    float* sW1 = sm;                   // D*D
    float* sW2 = sW1 + D * D;          // D*D
    float* sX  = sW2 + D * D;          // BM*SXS
    float* sH  = sX + BM * SXS;        // BM*SXS
    float* sB1 = sH + BM * SXS;        // D
    float* sB2 = sB1 + D;              // D
    int*   sIdx = reinterpret_cast<int*>(sB2 + D);   // BM

    int tid = threadIdx.x;

    // Load both weight matrices + biases once per block (persistent blocks).
    {
        const float4* w1v = reinterpret_cast<const float4*>(w1);
        const float4* w2v = reinterpret_cast<const float4*>(w2);
        float4* s1 = reinterpret_cast<float4*>(sW1);
        float4* s2 = reinterpret_cast<float4*>(sW2);
        for (int i = tid; i < D * D / 4; i += 256) { s1[i] = w1v[i]; s2[i] = w2v[i]; }
        if (tid < D) { sB1[tid] = b1[tid]; sB2[tid] = b2[tid]; }
    }

    int tcol = tid & 15;
    int trow = tid >> 4;
    int j0 = tcol * 8;
    int m0 = trow * 4;
    int ntiles = n / BM;   // n = 1e6, BM = 64 -> exact

    for (int tile = blockIdx.x; tile < ntiles; tile += gridDim.x) {
        long base = (long)tile * BM;
        __syncthreads();   // everyone finished previous sH/sIdx reads

        // stage x tile [BM x D] into smem (coalesced float4, row-major)
        {
            const float4* xv = reinterpret_cast<const float4*>(x + base * D);
            #pragma unroll
            for (int u = 0; u < 8; u++) {
                int i  = u * 256 + tid;   // 0..2047
                int m  = i >> 5;
                int kq = i & 31;
                *reinterpret_cast<float4*>(&sX[m * SXS + kq * 4]) = xv[i];
            }
            if (tid < BM) sIdx[tid] = idx[base + tid];
        }
        __syncthreads();

        unsigned long long acc[4][4];

        // ---- stage 1: H = relu(X @ W1 + b1) ----
        mma_stage(sX, sW1, m0, j0, acc);
        #pragma unroll
        for (int r = 0; r < 4; r++) {
            float2 f0 = unpack2(acc[r][0]), f1 = unpack2(acc[r][1]);
            float2 f2 = unpack2(acc[r][2]), f3 = unpack2(acc[r][3]);
            float4 o0, o1;
            o0.x = fmaxf(f0.x + sB1[j0 + 0], 0.f);
            o0.y = fmaxf(f0.y + sB1[j0 + 1], 0.f);
            o0.z = fmaxf(f1.x + sB1[j0 + 2], 0.f);
            o0.w = fmaxf(f1.y + sB1[j0 + 3], 0.f);
            o1.x = fmaxf(f2.x + sB1[j0 + 4], 0.f);
            o1.y = fmaxf(f2.y + sB1[j0 + 5], 0.f);
            o1.z = fmaxf(f3.x + sB1[j0 + 6], 0.f);
            o1.w = fmaxf(f3.y + sB1[j0 + 7], 0.f);
            *reinterpret_cast<float4*>(&sH[(m0 + r) * SXS + j0])     = o0;
            *reinterpret_cast<float4*>(&sH[(m0 + r) * SXS + j0 + 4]) = o1;
        }
        __syncthreads();

        // ---- stage 2: OUT = H @ W2 + b2 + rho_sum[idx] ----
        mma_stage(sH, sW2, m0, j0, acc);
        #pragma unroll
        for (int r = 0; r < 4; r++) {
            int seg = sIdx[m0 + r];
            const float4* rs = reinterpret_cast<const float4*>(&g_rho[(long)seg * D + j0]);
            float4 g0 = rs[0], g1 = rs[1];
            float2 f0 = unpack2(acc[r][0]), f1 = unpack2(acc[r][1]);
            float2 f2 = unpack2(acc[r][2]), f3 = unpack2(acc[r][3]);
            float4 o0, o1;
            o0.x = f0.x + sB2[j0 + 0] + g0.x;
            o0.y = f0.y + sB2[j0 + 1] + g0.y;
            o0.z = f1.x + sB2[j0 + 2] + g0.z;
            o0.w = f1.y + sB2[j0 + 3] + g0.w;
            o1.x = f2.x + sB2[j0 + 4] + g1.x;
            o1.y = f2.y + sB2[j0 + 5] + g1.y;
            o1.z = f3.x + sB2[j0 + 6] + g1.z;
            o1.w = f3.y + sB2[j0 + 7] + g1.w;
            float* op = out + (base + m0 + r) * D + j0;
            *reinterpret_cast<float4*>(op)     = o0;
            *reinterpret_cast<float4*>(op + 4) = o1;
        }
    }
}

// ---------------- launch ----------------------------------------------------
extern "C" void kernel_launch(void* const* d_in, const int* in_sizes, int n_in,
                              void* d_out, int out_size) {
    const float* x      = (const float*)d_in[0];
    const int*   idx    = (const int*)  d_in[1];
    const float* phi_w1 = (const float*)d_in[2];
    const float* phi_b1 = (const float*)d_in[3];
    const float* phi_w2 = (const float*)d_in[4];
    const float* phi_b2 = (const float*)d_in[5];
    const float* rho_w1 = (const float*)d_in[6];
    const float* rho_b1 = (const float*)d_in[7];
    const float* rho_w2 = (const float*)d_in[8];
    const float* rho_b2 = (const float*)d_in[9];
    float* out = (float*)d_out;
    int n = in_sizes[1];   // number of nodes (idx length)

    size_t smem_rho = (size_t)(D * D + 2 * RSEG * D + D) * sizeof(float);
    size_t smem_phi = (size_t)(2 * D * D + 2 * BM * SXS + 2 * D) * sizeof(float)
                    + BM * sizeof(int);

    cudaFuncSetAttribute(k_rho, cudaFuncAttributeMaxDynamicSharedMemorySize,
                         (int)smem_rho);
    cudaFuncSetAttribute(k_phi, cudaFuncAttributeMaxDynamicSharedMemorySize,
                         (int)smem_phi);

    // k0: zero segment accumulator (graph replays -> must re-zero every call)
    k_zero<<<(NSEG * D / 4 + 255) / 256, 256>>>();

    // k1: segment sum
    int segsum_blocks = (n + CH - 1) / CH;
    k_segsum<<<segsum_blocks, 128>>>(x, idx, n);

    // k2: rho MLP on segment sums
    k_rho<<<NSEG / RSEG, 128, smem_rho>>>(rho_w1, rho_b1, rho_w2, rho_b2);

    // k3: fused phi MLP + gather + add (persistent, 2 waves)
    k_phi<<<296, 256, smem_phi>>>(x, idx, phi_w1, phi_b1, phi_w2, phi_b2,
                                  out, n);
}

// round 3
// speedup vs baseline: 2.5237x; 2.5237x over previous
#include <cuda_runtime.h>
#include <cuda_bf16.h>
#include <cstdint>

#define D     128
#define NSEG  4096
#define BM    128
#define NTHR  256
#define CH    512
#define RSEG  32

#define WS    136            // padded bf16 row stride (272 bytes, 16B-multiple)
#define TILEB (BM * WS * 2)  // 34816 bytes per bf16 tile

// smem byte offsets
#define OXH  0
#define OXL  (TILEB)
#define OW1H (2 * TILEB)
#define OW1L (3 * TILEB)
#define OW2H (4 * TILEB)
#define OW2L (5 * TILEB)
#define OB1  (6 * TILEB)
#define OB2  (6 * TILEB + 512)
#define OIDX (6 * TILEB + 1024)
#define SMEM_PHI (6 * TILEB + 1536)

// ---------------- scratch ----------------------------------------------------
__device__ float g_xsum[NSEG * D];
__device__ float g_rho [NSEG * D];

// ---------------- helpers ----------------------------------------------------
__device__ __forceinline__ uint32_t smem_u32(const void* p) {
    uint32_t a;
    asm("{ .reg .u64 t; cvta.to.shared.u64 t, %1; cvt.u32.u64 %0, t; }"
        : "=r"(a) : "l"(p));
    return a;
}
__device__ __forceinline__ void ldsm_x4(uint32_t r[4], uint32_t addr) {
    asm volatile("ldmatrix.sync.aligned.m8n8.x4.shared.b16 {%0,%1,%2,%3}, [%4];"
                 : "=r"(r[0]), "=r"(r[1]), "=r"(r[2]), "=r"(r[3]) : "r"(addr));
}
__device__ __forceinline__ void mma_bf16(float c[4], const uint32_t a[4],
                                         const uint32_t* b) {
    asm volatile("mma.sync.aligned.m16n8k16.row.col.f32.bf16.bf16.f32 "
                 "{%0,%1,%2,%3}, {%4,%5,%6,%7}, {%8,%9}, {%0,%1,%2,%3};"
                 : "+f"(c[0]), "+f"(c[1]), "+f"(c[2]), "+f"(c[3])
                 : "r"(a[0]), "r"(a[1]), "r"(a[2]), "r"(a[3]),
                   "r"(b[0]), "r"(b[1]));
}
__device__ __forceinline__ void bsplit(float v, uint32_t& h, uint32_t& l) {
    __nv_bfloat16 bh = __float2bfloat16(v);
    h = (uint32_t)__bfloat16_as_ushort(bh);
    float r = v - __bfloat162float(bh);
    l = (uint32_t)__bfloat16_as_ushort(__float2bfloat16(r));
}

// ---------------- k0: zero ---------------------------------------------------
__global__ void k_zero() {
    int i = blockIdx.x * blockDim.x + threadIdx.x;
    if (i < NSEG * D / 4)
        reinterpret_cast<float4*>(g_xsum)[i] = make_float4(0.f, 0.f, 0.f, 0.f);
}

// ---------------- k1: segment sum (idx sorted) --------------------------------
__global__ void k_segsum(const float* __restrict__ x,
                         const int*   __restrict__ idx, int n) {
    int f = threadIdx.x;
    long start = (long)blockIdx.x * CH;
    if (start >= n) return;
    long end = start + CH; if (end > n) end = n;

    int   cur = __ldg(&idx[start]);
    float acc = 0.f;
    long nn = start;
    for (; nn + 8 <= end; nn += 8) {
        float v[8]; int s[8];
        #pragma unroll
        for (int u = 0; u < 8; u++) {
            s[u] = __ldg(&idx[nn + u]);
            v[u] = __ldg(&x[(nn + u) * D + f]);
        }
        #pragma unroll
        for (int u = 0; u < 8; u++) {
            if (s[u] != cur) {
                atomicAdd(&g_xsum[(long)cur * D + f], acc);
                acc = 0.f; cur = s[u];
            }
            acc += v[u];
        }
    }
    for (; nn < end; ++nn) {
        int s = __ldg(&idx[nn]);
        float v = __ldg(&x[nn * D + f]);
        if (s != cur) {
            atomicAdd(&g_xsum[(long)cur * D + f], acc);
            acc = 0.f; cur = s;
        }
        acc += v;
    }
    atomicAdd(&g_xsum[(long)cur * D + f], acc);
}

// ---------------- k2: rho MLP on segment sums ----------------------------------
__global__ void k_rho(const float* __restrict__ w1, const float* __restrict__ b1,
                      const float* __restrict__ w2, const float* __restrict__ b2) {
    extern __shared__ float sm[];
    float* sW = sm;
    float* sX = sW + D * D;
    float* sH = sX + RSEG * D;
    float* sB = sH + RSEG * D;
    int j = threadIdx.x;
    int seg0 = blockIdx.x * RSEG;

    for (int r = 0; r < RSEG; r++)
        sX[r * D + j] = g_xsum[(seg0 + r) * D + j];
    for (int i = j; i < D * D; i += blockDim.x) sW[i] = w1[i];
    sB[j] = b1[j];
    __syncthreads();

    for (int r = 0; r < RSEG; r++) {
        float acc = sB[j];
        #pragma unroll 8
        for (int k = 0; k < D; k++) acc += sX[r * D + k] * sW[k * D + j];
        sH[r * D + j] = fmaxf(acc, 0.f);
    }
    __syncthreads();
    for (int i = j; i < D * D; i += blockDim.x) sW[i] = w2[i];
    sB[j] = b2[j];
    __syncthreads();

    for (int r = 0; r < RSEG; r++) {
        float acc = sB[j];
        #pragma unroll 8
        for (int k = 0; k < D; k++) acc += sH[r * D + k] * sW[k * D + j];
        g_rho[(seg0 + r) * D + j] = acc;
    }
}

// ---------------- MMA layer: acc += 3-pass bf16 split GEMM --------------------
// A tiles at (sb+aH, sb+aL): 128x128 bf16, row stride WS.
// B tiles at (sb+bH, sb+bL): W^T [j][k] layout, row stride WS.
__device__ __forceinline__ void mma_layer(uint32_t sb, uint32_t aH, uint32_t aL,
                                          uint32_t bH, uint32_t bL,
                                          uint32_t aRow, uint32_t bRow,
                                          float acc[2][8][4]) {
    #pragma unroll
    for (int k = 0; k < 8; k++) {
        uint32_t ah[2][4], al[2][4];
        ldsm_x4(ah[0], sb + aH + aRow + k * 32);
        ldsm_x4(ah[1], sb + aH + aRow + 16 * (WS * 2) + k * 32);
        ldsm_x4(al[0], sb + aL + aRow + k * 32);
        ldsm_x4(al[1], sb + aL + aRow + 16 * (WS * 2) + k * 32);
        #pragma unroll
        for (int np = 0; np < 4; np++) {
            uint32_t bh[4], bl[4];
            ldsm_x4(bh, sb + bH + bRow + np * 16 * (WS * 2) + k * 32);
            ldsm_x4(bl, sb + bL + bRow + np * 16 * (WS * 2) + k * 32);
            #pragma unroll
            for (int mt = 0; mt < 2; mt++) {
                mma_bf16(acc[mt][2 * np],     ah[mt], bh);
                mma_bf16(acc[mt][2 * np + 1], ah[mt], bh + 2);
                mma_bf16(acc[mt][2 * np],     ah[mt], bl);
                mma_bf16(acc[mt][2 * np + 1], ah[mt], bl + 2);
                mma_bf16(acc[mt][2 * np],     al[mt], bh);
                mma_bf16(acc[mt][2 * np + 1], al[mt], bh + 2);
            }
        }
    }
}

// ---------------- k3: phi MLP (HMMA) + fused rho gather ------------------------
__global__ __launch_bounds__(NTHR, 1)
void k_phi(const float* __restrict__ x, const int* __restrict__ idx,
           const float* __restrict__ w1, const float* __restrict__ b1,
           const float* __restrict__ w2, const float* __restrict__ b2,
           float* __restrict__ out, int n) {
    extern __shared__ char smem[];
    const uint32_t sb = smem_u32(smem);
    int tid = threadIdx.x, wid = tid >> 5, lane = tid & 31;
    int wm = wid >> 1, wn = wid & 1;      // 4 x 2 warp grid

    // ---- prologue: weights -> W^T bf16 hi/lo, biases ----
    for (int i = tid; i < D * D; i += NTHR) {      // i = k*128 + j
        int k = i >> 7, j = i & 127;
        uint32_t h, l, h2, l2;
        bsplit(w1[i], h, l);
        bsplit(w2[i], h2, l2);
        uint32_t o = (uint32_t)(j * WS + k) * 2;
        *(unsigned short*)(smem + OW1H + o) = (unsigned short)h;
        *(unsigned short*)(smem + OW1L + o) = (unsigned short)l;
        *(unsigned short*)(smem + OW2H + o) = (unsigned short)h2;
        *(unsigned short*)(smem + OW2L + o) = (unsigned short)l2;
    }
    if (tid < D) {
        ((float*)(smem + OB1))[tid] = b1[tid];
        ((float*)(smem + OB2))[tid] = b2[tid];
    }

    const float* sB1 = (const float*)(smem + OB1);
    const float* sB2 = (const float*)(smem + OB2);
    int* sIdx = (int*)(smem + OIDX);

    // per-warp ldmatrix row bases (bytes)
    const uint32_t aRow = (uint32_t)(wm * 32 + (lane & 15)) * (WS * 2)
                        + (uint32_t)((lane >> 4) << 4);
    const uint32_t bRow = (uint32_t)(wn * 64 + (lane & 7) + ((lane >> 4) << 3)) * (WS * 2)
                        + (uint32_t)(((lane >> 3) & 1) << 4);

    const int ntiles = (n + BM - 1) / BM;

    for (int tile = blockIdx.x; tile < ntiles; tile += gridDim.x) {
        long base = (long)tile * BM;
        __syncthreads();   // previous tile fully consumed

        // ---- stage X tile -> bf16 hi/lo ----
        const float4* xv = (const float4*)x;
        #pragma unroll
        for (int it = 0; it < 16; ++it) {
            int i = it * NTHR + tid;          // 0..4095 float4 slots
            int m = i >> 5, kq = i & 31;
            float4 v = make_float4(0.f, 0.f, 0.f, 0.f);
            if (base + m < n) v = xv[(base + m) * 32 + kq];
            uint32_t h0,l0,h1,l1,h2,l2,h3,l3;
            bsplit(v.x,h0,l0); bsplit(v.y,h1,l1); bsplit(v.z,h2,l2); bsplit(v.w,h3,l3);
            uint32_t o = (uint32_t)(m * WS + kq * 4) * 2;
            *(uint2*)(smem + OXH + o) = make_uint2(h0 | (h1 << 16), h2 | (h3 << 16));
            *(uint2*)(smem + OXL + o) = make_uint2(l0 | (l1 << 16), l2 | (l3 << 16));
        }
        if (tid < BM) {
            int s = 0;
            if (base + tid < n) s = idx[base + tid];
            sIdx[tid] = s;
        }
        __syncthreads();

        // ---- layer 1 ----
        float acc[2][8][4];
        #pragma unroll
        for (int a = 0; a < 2; a++)
            #pragma unroll
            for (int b = 0; b < 8; b++)
                #pragma unroll
                for (int c = 0; c < 4; c++) acc[a][b][c] = 0.f;
        mma_layer(sb, OXH, OXL, OW1H, OW1L, aRow, bRow, acc);
        __syncthreads();   // all warps done reading X

        // ---- epilogue 1: relu(.+b1) -> bf16 hi/lo back into X buffers ----
        #pragma unroll
        for (int mt = 0; mt < 2; mt++) {
            int r0 = wm * 32 + mt * 16 + (lane >> 2);
            #pragma unroll
            for (int nt = 0; nt < 8; nt++) {
                int col = wn * 64 + nt * 8 + (lane & 3) * 2;
                float* c = acc[mt][nt];
                float v0 = fmaxf(c[0] + sB1[col],     0.f);
                float v1 = fmaxf(c[1] + sB1[col + 1], 0.f);
                float v2 = fmaxf(c[2] + sB1[col],     0.f);
                float v3 = fmaxf(c[3] + sB1[col + 1], 0.f);
                uint32_t h0,l0,h1,l1,h2,l2,h3,l3;
                bsplit(v0,h0,l0); bsplit(v1,h1,l1);
                bsplit(v2,h2,l2); bsplit(v3,h3,l3);
                uint32_t oA = (uint32_t)(r0 * WS + col) * 2;
                uint32_t oB = (uint32_t)((r0 + 8) * WS + col) * 2;
                *(uint32_t*)(smem + OXH + oA) = h0 | (h1 << 16);
                *(uint32_t*)(smem + OXL + oA) = l0 | (l1 << 16);
                *(uint32_t*)(smem + OXH + oB) = h2 | (h3 << 16);
                *(uint32_t*)(smem + OXL + oB) = l2 | (l3 << 16);
            }
        }
        __syncthreads();

        // ---- layer 2 ----
        #pragma unroll
        for (int a = 0; a < 2; a++)
            #pragma unroll
            for (int b = 0; b < 8; b++)
                #pragma unroll
                for (int c = 0; c < 4; c++) acc[a][b][c] = 0.f;
        mma_layer(sb, OXH, OXL, OW2H, OW2L, aRow, bRow, acc);

        // ---- writeout: + b2 + rho[idx], straight from fragments ----
        #pragma unroll
        for (int mt = 0; mt < 2; mt++) {
            int rl = wm * 32 + mt * 16 + (lane >> 2);
            #pragma unroll
            for (int half = 0; half < 2; half++) {
                int row = rl + half * 8;
                long grow = base + row;
                if (grow < n) {
                    int seg = sIdx[row];
                    #pragma unroll
                    for (int nt = 0; nt < 8; nt++) {
                        int col = wn * 64 + nt * 8 + (lane & 3) * 2;
                        float* c = acc[mt][nt];
                        float2 g = *(const float2*)&g_rho[(long)seg * D + col];
                        float2 o;
                        o.x = c[2 * half]     + sB2[col]     + g.x;
                        o.y = c[2 * half + 1] + sB2[col + 1] + g.y;
                        *(float2*)&out[grow * D + col] = o;
                    }
                }
            }
        }
    }
}

// ---------------- launch --------------------------------------------------------
extern "C" void kernel_launch(void* const* d_in, const int* in_sizes, int n_in,
                              void* d_out, int out_size) {
    const float* x      = (const float*)d_in[0];
    const int*   idx    = (const int*)  d_in[1];
    const float* phi_w1 = (const float*)d_in[2];
    const float* phi_b1 = (const float*)d_in[3];
    const float* phi_w2 = (const float*)d_in[4];
    const float* phi_b2 = (const float*)d_in[5];
    const float* rho_w1 = (const float*)d_in[6];
    const float* rho_b1 = (const float*)d_in[7];
    const float* rho_w2 = (const float*)d_in[8];
    const float* rho_b2 = (const float*)d_in[9];
    float* out = (float*)d_out;
    int n = in_sizes[1];

    size_t smem_rho = (size_t)(D * D + 2 * RSEG * D + D) * sizeof(float);
    cudaFuncSetAttribute(k_rho, cudaFuncAttributeMaxDynamicSharedMemorySize,
                         (int)smem_rho);
    cudaFuncSetAttribute(k_phi, cudaFuncAttributeMaxDynamicSharedMemorySize,
                         SMEM_PHI);

    k_zero<<<(NSEG * D / 4 + 255) / 256, 256>>>();

    int segsum_blocks = (n + CH - 1) / CH;
    k_segsum<<<segsum_blocks, 128>>>(x, idx, n);

    k_rho<<<NSEG / RSEG, 128, smem_rho>>>(rho_w1, rho_b1, rho_w2, rho_b2);

    k_phi<<<152, NTHR, SMEM_PHI>>>(x, idx, phi_w1, phi_b1, phi_w2, phi_b2,
                                   out, n);
}

// round 4
// speedup vs baseline: 2.9108x; 1.1534x over previous
#include <cuda_runtime.h>
#include <cuda_bf16.h>
#include <cstdint>

#define D     128
#define NSEG  4096
#define BM    128
#define NTHR  512
#define CH    512
#define RSEG  32

#define WS    136            // padded bf16 row stride (272 bytes, 16B-multiple)
#define TILEB (BM * WS * 2)  // 34816 bytes per bf16 tile

// smem byte offsets
#define OXH  0
#define OXL  (TILEB)
#define OW1H (2 * TILEB)
#define OW1L (3 * TILEB)
#define OW2H (4 * TILEB)
#define OW2L (5 * TILEB)
#define OB1  (6 * TILEB)
#define OB2  (6 * TILEB + 512)
#define OIDX (6 * TILEB + 1024)
#define SMEM_PHI (6 * TILEB + 1536)

// ---------------- scratch ----------------------------------------------------
__device__ float g_xsum[NSEG * D];
__device__ float g_rho [NSEG * D];

// ---------------- helpers ----------------------------------------------------
__device__ __forceinline__ uint32_t smem_u32(const void* p) {
    uint32_t a;
    asm("{ .reg .u64 t; cvta.to.shared.u64 t, %1; cvt.u32.u64 %0, t; }"
        : "=r"(a) : "l"(p));
    return a;
}
__device__ __forceinline__ void ldsm_x4(uint32_t r[4], uint32_t addr) {
    asm volatile("ldmatrix.sync.aligned.m8n8.x4.shared.b16 {%0,%1,%2,%3}, [%4];"
                 : "=r"(r[0]), "=r"(r[1]), "=r"(r[2]), "=r"(r[3]) : "r"(addr));
}
__device__ __forceinline__ void mma_bf16(float c[4], const uint32_t a[4],
                                         const uint32_t* b) {
    asm volatile("mma.sync.aligned.m16n8k16.row.col.f32.bf16.bf16.f32 "
                 "{%0,%1,%2,%3}, {%4,%5,%6,%7}, {%8,%9}, {%0,%1,%2,%3};"
                 : "+f"(c[0]), "+f"(c[1]), "+f"(c[2]), "+f"(c[3])
                 : "r"(a[0]), "r"(a[1]), "r"(a[2]), "r"(a[3]),
                   "r"(b[0]), "r"(b[1]));
}
__device__ __forceinline__ void bsplit(float v, uint32_t& h, uint32_t& l) {
    __nv_bfloat16 bh = __float2bfloat16(v);
    h = (uint32_t)__bfloat16_as_ushort(bh);
    float r = v - __bfloat162float(bh);
    l = (uint32_t)__bfloat16_as_ushort(__float2bfloat16(r));
}

// ---------------- k0: zero ---------------------------------------------------
__global__ void k_zero() {
    int i = blockIdx.x * blockDim.x + threadIdx.x;
    if (i < NSEG * D / 4)
        reinterpret_cast<float4*>(g_xsum)[i] = make_float4(0.f, 0.f, 0.f, 0.f);
}

// ---------------- k1: segment sum (idx sorted) --------------------------------
__global__ void k_segsum(const float* __restrict__ x,
                         const int*   __restrict__ idx, int n) {
    int f = threadIdx.x;
    long start = (long)blockIdx.x * CH;
    if (start >= n) return;
    long end = start + CH; if (end > n) end = n;

    int   cur = __ldg(&idx[start]);
    float acc = 0.f;
    long nn = start;
    for (; nn + 8 <= end; nn += 8) {
        float v[8]; int s[8];
        #pragma unroll
        for (int u = 0; u < 8; u++) {
            s[u] = __ldg(&idx[nn + u]);
            v[u] = __ldg(&x[(nn + u) * D + f]);
        }
        #pragma unroll
        for (int u = 0; u < 8; u++) {
            if (s[u] != cur) {
                atomicAdd(&g_xsum[(long)cur * D + f], acc);
                acc = 0.f; cur = s[u];
            }
            acc += v[u];
        }
    }
    for (; nn < end; ++nn) {
        int s = __ldg(&idx[nn]);
        float v = __ldg(&x[nn * D + f]);
        if (s != cur) {
            atomicAdd(&g_xsum[(long)cur * D + f], acc);
            acc = 0.f; cur = s;
        }
        acc += v;
    }
    atomicAdd(&g_xsum[(long)cur * D + f], acc);
}

// ---------------- k2: rho MLP on segment sums ----------------------------------
__global__ void k_rho(const float* __restrict__ w1, const float* __restrict__ b1,
                      const float* __restrict__ w2, const float* __restrict__ b2) {
    extern __shared__ float sm[];
    float* sW = sm;
    float* sX = sW + D * D;
    float* sH = sX + RSEG * D;
    float* sB = sH + RSEG * D;
    int j = threadIdx.x;
    int seg0 = blockIdx.x * RSEG;

    for (int r = 0; r < RSEG; r++)
        sX[r * D + j] = g_xsum[(seg0 + r) * D + j];
    for (int i = j; i < D * D; i += blockDim.x) sW[i] = w1[i];
    sB[j] = b1[j];
    __syncthreads();

    for (int r = 0; r < RSEG; r++) {
        float acc = sB[j];
        #pragma unroll 8
        for (int k = 0; k < D; k++) acc += sX[r * D + k] * sW[k * D + j];
        sH[r * D + j] = fmaxf(acc, 0.f);
    }
    __syncthreads();
    for (int i = j; i < D * D; i += blockDim.x) sW[i] = w2[i];
    sB[j] = b2[j];
    __syncthreads();

    for (int r = 0; r < RSEG; r++) {
        float acc = sB[j];
        #pragma unroll 8
        for (int k = 0; k < D; k++) acc += sH[r * D + k] * sW[k * D + j];
        g_rho[(seg0 + r) * D + j] = acc;
    }
}

// ---------------- MMA layer: acc += 3-pass bf16 split GEMM --------------------
// Warp tile 32(m) x 32(n).  A at (aH,aL): [128 x 128] bf16, stride WS.
// B at (bH,bL): W^T [j][k], stride WS.
__device__ __forceinline__ void mma_layer(uint32_t sb, uint32_t aH, uint32_t aL,
                                          uint32_t bH, uint32_t bL,
                                          uint32_t aRow, uint32_t bRow,
                                          float acc[2][4][4]) {
    #pragma unroll
    for (int k = 0; k < 8; k++) {
        uint32_t ah[2][4], al[2][4];
        ldsm_x4(ah[0], sb + aH + aRow + k * 32);
        ldsm_x4(ah[1], sb + aH + aRow + 16 * (WS * 2) + k * 32);
        ldsm_x4(al[0], sb + aL + aRow + k * 32);
        ldsm_x4(al[1], sb + aL + aRow + 16 * (WS * 2) + k * 32);
        #pragma unroll
        for (int np = 0; np < 2; np++) {
            uint32_t bh[4], bl[4];
            ldsm_x4(bh, sb + bH + bRow + np * 16 * (WS * 2) + k * 32);
            ldsm_x4(bl, sb + bL + bRow + np * 16 * (WS * 2) + k * 32);
            #pragma unroll
            for (int mt = 0; mt < 2; mt++) {
                mma_bf16(acc[mt][2 * np],     ah[mt], bh);
                mma_bf16(acc[mt][2 * np + 1], ah[mt], bh + 2);
                mma_bf16(acc[mt][2 * np],     ah[mt], bl);
                mma_bf16(acc[mt][2 * np + 1], ah[mt], bl + 2);
                mma_bf16(acc[mt][2 * np],     al[mt], bh);
                mma_bf16(acc[mt][2 * np + 1], al[mt], bh + 2);
            }
        }
    }
}

// ---------------- k3: phi MLP (HMMA) + fused rho gather ------------------------
__global__ __launch_bounds__(NTHR, 1)
void k_phi(const float* __restrict__ x, const int* __restrict__ idx,
           const float* __restrict__ w1, const float* __restrict__ b1,
           const float* __restrict__ w2, const float* __restrict__ b2,
           float* __restrict__ out, int n) {
    extern __shared__ char smem[];
    const uint32_t sb = smem_u32(smem);
    int tid = threadIdx.x, wid = tid >> 5, lane = tid & 31;
    int wm = wid >> 2, wn = wid & 3;      // 4 x 4 warp grid, warp tile 32x32

    // ---- prologue: weights -> W^T bf16 hi/lo, biases ----
    for (int i = tid; i < D * D; i += NTHR) {      // i = k*128 + j
        int k = i >> 7, j = i & 127;
        uint32_t h, l, h2, l2;
        bsplit(w1[i], h, l);
        bsplit(w2[i], h2, l2);
        uint32_t o = (uint32_t)(j * WS + k) * 2;
        *(unsigned short*)(smem + OW1H + o) = (unsigned short)h;
        *(unsigned short*)(smem + OW1L + o) = (unsigned short)l;
        *(unsigned short*)(smem + OW2H + o) = (unsigned short)h2;
        *(unsigned short*)(smem + OW2L + o) = (unsigned short)l2;
    }
    if (tid < D) {
        ((float*)(smem + OB1))[tid] = b1[tid];
        ((float*)(smem + OB2))[tid] = b2[tid];
    }

    const float* sB1 = (const float*)(smem + OB1);
    const float* sB2 = (const float*)(smem + OB2);
    int* sIdx = (int*)(smem + OIDX);

    // per-warp ldmatrix row bases (bytes)
    const uint32_t aRow = (uint32_t)(wm * 32 + (lane & 15)) * (WS * 2)
                        + (uint32_t)((lane >> 4) << 4);
    const uint32_t bRow = (uint32_t)(wn * 32 + (lane & 7) + ((lane >> 4) << 3)) * (WS * 2)
                        + (uint32_t)(((lane >> 3) & 1) << 4);

    const int ntiles = (n + BM - 1) / BM;

    for (int tile = blockIdx.x; tile < ntiles; tile += gridDim.x) {
        long base = (long)tile * BM;
        __syncthreads();   // previous tile fully consumed

        // ---- stage X tile -> bf16 hi/lo ----
        const float4* xv = (const float4*)x;
        #pragma unroll
        for (int it = 0; it < 8; ++it) {
            int i = it * NTHR + tid;          // 0..4095 float4 slots
            int m = i >> 5, kq = i & 31;
            float4 v = make_float4(0.f, 0.f, 0.f, 0.f);
            if (base + m < n) v = xv[(base + m) * 32 + kq];
            uint32_t h0,l0,h1,l1,h2,l2,h3,l3;
            bsplit(v.x,h0,l0); bsplit(v.y,h1,l1); bsplit(v.z,h2,l2); bsplit(v.w,h3,l3);
            uint32_t o = (uint32_t)(m * WS + kq * 4) * 2;
            *(uint2*)(smem + OXH + o) = make_uint2(h0 | (h1 << 16), h2 | (h3 << 16));
            *(uint2*)(smem + OXL + o) = make_uint2(l0 | (l1 << 16), l2 | (l3 << 16));
        }
        if (tid < BM) {
            int s = 0;
            if (base + tid < n) s = idx[base + tid];
            sIdx[tid] = s;
        }
        __syncthreads();

        // ---- layer 1 ----
        float acc[2][4][4];
        #pragma unroll
        for (int a = 0; a < 2; a++)
            #pragma unroll
            for (int b = 0; b < 4; b++)
                #pragma unroll
                for (int c = 0; c < 4; c++) acc[a][b][c] = 0.f;
        mma_layer(sb, OXH, OXL, OW1H, OW1L, aRow, bRow, acc);
        __syncthreads();   // all warps done reading X

        // ---- epilogue 1: relu(.+b1) -> bf16 hi/lo back into X buffers ----
        #pragma unroll
        for (int mt = 0; mt < 2; mt++) {
            int r0 = wm * 32 + mt * 16 + (lane >> 2);
            #pragma unroll
            for (int nt = 0; nt < 4; nt++) {
                int col = wn * 32 + nt * 8 + (lane & 3) * 2;
                float* c = acc[mt][nt];
                float v0 = fmaxf(c[0] + sB1[col],     0.f);
                float v1 = fmaxf(c[1] + sB1[col + 1], 0.f);
                float v2 = fmaxf(c[2] + sB1[col],     0.f);
                float v3 = fmaxf(c[3] + sB1[col + 1], 0.f);
                uint32_t h0,l0,h1,l1,h2,l2,h3,l3;
                bsplit(v0,h0,l0); bsplit(v1,h1,l1);
                bsplit(v2,h2,l2); bsplit(v3,h3,l3);
                uint32_t oA = (uint32_t)(r0 * WS + col) * 2;
                uint32_t oB = (uint32_t)((r0 + 8) * WS + col) * 2;
                *(uint32_t*)(smem + OXH + oA) = h0 | (h1 << 16);
                *(uint32_t*)(smem + OXL + oA) = l0 | (l1 << 16);
                *(uint32_t*)(smem + OXH + oB) = h2 | (h3 << 16);
                *(uint32_t*)(smem + OXL + oB) = l2 | (l3 << 16);
            }
        }
        __syncthreads();

        // ---- layer 2 ----
        #pragma unroll
        for (int a = 0; a < 2; a++)
            #pragma unroll
            for (int b = 0; b < 4; b++)
                #pragma unroll
                for (int c = 0; c < 4; c++) acc[a][b][c] = 0.f;
        mma_layer(sb, OXH, OXL, OW2H, OW2L, aRow, bRow, acc);

        // ---- writeout: + b2 + rho[idx], straight from fragments ----
        #pragma unroll
        for (int mt = 0; mt < 2; mt++) {
            int rl = wm * 32 + mt * 16 + (lane >> 2);
            #pragma unroll
            for (int half = 0; half < 2; half++) {
                int row = rl + half * 8;
                long grow = base + row;
                if (grow < n) {
                    int seg = sIdx[row];
                    #pragma unroll
                    for (int nt = 0; nt < 4; nt++) {
                        int col = wn * 32 + nt * 8 + (lane & 3) * 2;
                        float* c = acc[mt][nt];
                        float2 g = *(const float2*)&g_rho[(long)seg * D + col];
                        float2 o;
                        o.x = c[2 * half]     + sB2[col]     + g.x;
                        o.y = c[2 * half + 1] + sB2[col + 1] + g.y;
                        *(float2*)&out[grow * D + col] = o;
                    }
                }
            }
        }
    }
}

// ---------------- launch --------------------------------------------------------
extern "C" void kernel_launch(void* const* d_in, const int* in_sizes, int n_in,
                              void* d_out, int out_size) {
    const float* x      = (const float*)d_in[0];
    const int*   idx    = (const int*)  d_in[1];
    const float* phi_w1 = (const float*)d_in[2];
    const float* phi_b1 = (const float*)d_in[3];
    const float* phi_w2 = (const float*)d_in[4];
    const float* phi_b2 = (const float*)d_in[5];
    const float* rho_w1 = (const float*)d_in[6];
    const float* rho_b1 = (const float*)d_in[7];
    const float* rho_w2 = (const float*)d_in[8];
    const float* rho_b2 = (const float*)d_in[9];
    float* out = (float*)d_out;
    int n = in_sizes[1];

    size_t smem_rho = (size_t)(D * D + 2 * RSEG * D + D) * sizeof(float);
    cudaFuncSetAttribute(k_rho, cudaFuncAttributeMaxDynamicSharedMemorySize,
                         (int)smem_rho);
    cudaFuncSetAttribute(k_phi, cudaFuncAttributeMaxDynamicSharedMemorySize,
                         SMEM_PHI);

    k_zero<<<(NSEG * D / 4 + 255) / 256, 256>>>();

    int segsum_blocks = (n + CH - 1) / CH;
    k_segsum<<<segsum_blocks, 128>>>(x, idx, n);

    k_rho<<<NSEG / RSEG, 128, smem_rho>>>(rho_w1, rho_b1, rho_w2, rho_b2);

    k_phi<<<152, NTHR, SMEM_PHI>>>(x, idx, phi_w1, phi_b1, phi_w2, phi_b2,
                                   out, n);
}